// round 13
// baseline (speedup 1.0000x reference)
#include <cuda_runtime.h>
#include <cuda_bf16.h>
#include <math.h>

// Problem constants
#define Bsz   2
#define Sseq  2048
#define HIDD  1024
#define Hh    16
#define NBQ   32
#define KSEL  8
#define BLK   64
#define Dd    64

#define QKV_ELEMS (Bsz * Hh * NBQ * BLK * Dd)   // 4,194,304 per tensor

// TF32 GEMM inputs (fp32 payload with tf32 rounding, stored as u32)
__device__ __align__(256) unsigned g_xt[Bsz * Sseq * HIDD];
__device__ __align__(256) unsigned g_wt3[3 * HIDD * HIDD];   // [z][n][k]

// QKV outputs, bf16 hi/lo, layout [z][b,h,blk][row][d]  (attention inputs)
__device__ __align__(256) __nv_bfloat16 g_ohi[3 * QKV_ELEMS];
__device__ __align__(256) __nv_bfloat16 g_olo[3 * QKV_ELEMS];

// ---------------------------------------------------------------------------
// Generic-PTX helpers
// ---------------------------------------------------------------------------
static __device__ __forceinline__ unsigned smem_u32(const void* p) {
    unsigned a;
    asm("{ .reg .u64 t; cvta.to.shared.u64 t, %1; cvt.u32.u64 %0, t; }"
        : "=r"(a) : "l"(p));
    return a;
}

static __device__ __forceinline__ void cp16(unsigned dst, const void* src) {
    asm volatile("cp.async.cg.shared.global [%0], [%1], 16;"
                 :: "r"(dst), "l"(src));
}
static __device__ __forceinline__ void cp_commit() {
    asm volatile("cp.async.commit_group;");
}
static __device__ __forceinline__ void cp_wait0() {
    asm volatile("cp.async.wait_group 0;" ::: "memory");
}

static __device__ __forceinline__ void ldm_x4(unsigned r[4], unsigned addr) {
    asm volatile("ldmatrix.sync.aligned.m8n8.x4.shared.b16 {%0,%1,%2,%3}, [%4];"
                 : "=r"(r[0]), "=r"(r[1]), "=r"(r[2]), "=r"(r[3]) : "r"(addr));
}
static __device__ __forceinline__ void ldm_x4t(unsigned r[4], unsigned addr) {
    asm volatile("ldmatrix.sync.aligned.m8n8.x4.trans.shared.b16 {%0,%1,%2,%3}, [%4];"
                 : "=r"(r[0]), "=r"(r[1]), "=r"(r[2]), "=r"(r[3]) : "r"(addr));
}

static __device__ __forceinline__ void mma16816(float c[4], const unsigned a[4],
                                                unsigned b0, unsigned b1) {
    asm volatile(
        "mma.sync.aligned.m16n8k16.row.col.f32.bf16.bf16.f32 "
        "{%0,%1,%2,%3}, {%4,%5,%6,%7}, {%8,%9}, {%0,%1,%2,%3};"
        : "+f"(c[0]), "+f"(c[1]), "+f"(c[2]), "+f"(c[3])
        : "r"(a[0]), "r"(a[1]), "r"(a[2]), "r"(a[3]), "r"(b0), "r"(b1));
}

static __device__ __forceinline__ void mma16808(float c[4], const unsigned a[4],
                                                unsigned b0, unsigned b1) {
    asm volatile(
        "mma.sync.aligned.m16n8k8.row.col.f32.tf32.tf32.f32 "
        "{%0,%1,%2,%3}, {%4,%5,%6,%7}, {%8,%9}, {%0,%1,%2,%3};"
        : "+f"(c[0]), "+f"(c[1]), "+f"(c[2]), "+f"(c[3])
        : "r"(a[0]), "r"(a[1]), "r"(a[2]), "r"(a[3]), "r"(b0), "r"(b1));
}

static __device__ __forceinline__ unsigned f2tf32(float f) {
    unsigned u;
    asm("cvt.rna.tf32.f32 %0, %1;" : "=r"(u) : "f"(f));
    return u;
}

static __device__ __forceinline__ unsigned b2u(__nv_bfloat162 v) {
    return *reinterpret_cast<unsigned*>(&v);
}

// ---------------------------------------------------------------------------
// Conversion kernels: fp32 -> tf32
// ---------------------------------------------------------------------------
__global__ __launch_bounds__(256)
void cvt_x_kernel(const float* __restrict__ X)
{
    int i4 = (blockIdx.x * 256 + threadIdx.x) << 2;
    float4 v = *(const float4*)(X + i4);
    uint4 o;
    o.x = f2tf32(v.x);
    o.y = f2tf32(v.y);
    o.z = f2tf32(v.z);
    o.w = f2tf32(v.w);
    *(uint4*)(g_xt + i4) = o;
}

__global__ __launch_bounds__(256)
void cvt_w_kernel(const float* __restrict__ Wq, const float* __restrict__ Wk,
                  const float* __restrict__ Wv)
{
    __shared__ float t[32][33];
    const float* W = (blockIdx.z == 0) ? Wq : (blockIdx.z == 1) ? Wk : Wv;
    const int k0 = blockIdx.x * 32;
    const int n0 = blockIdx.y * 32;
    const int tx = threadIdx.x;
    const int ty = threadIdx.y;

#pragma unroll
    for (int r = 0; r < 32; r += 8)
        t[ty + r][tx] = W[(size_t)(k0 + ty + r) * HIDD + n0 + tx];
    __syncthreads();

    const size_t ob = ((size_t)blockIdx.z << 20);
#pragma unroll
    for (int r = 0; r < 32; r += 8) {
        g_wt3[ob + (size_t)(n0 + ty + r) * HIDD + k0 + tx] = f2tf32(t[tx][ty + r]);
    }
}

// ---------------------------------------------------------------------------
// QKV GEMM via mma.sync TF32, single pass.
// CTA 128x128, BK=32 (fp32), 128 threads = 4 warps (2x2), warp tile 64x64.
// 2-stage cp.async pipeline (64 KB smem) -> 3 CTAs/SM for latency hiding.
// ---------------------------------------------------------------------------
#define ATILE 16384
#define QSTAGE 32768
#define GEMM_SMEM_BYTES (2 * QSTAGE)     // 65536

// SW128 swizzle (rows of 128 B = 32 fp32)
static __device__ __forceinline__ unsigned swz(int r, int c16) {
    return (unsigned)((r << 7) + ((c16 ^ (r & 7)) << 4));
}

__global__ __launch_bounds__(128, 3)
void qkv_mma_kernel(const float* __restrict__ bq, const float* __restrict__ bk,
                    const float* __restrict__ bv)
{
    extern __shared__ char sm[];
    const unsigned sbase = smem_u32(sm);
    const int tid  = threadIdx.x;
    const int lane = tid & 31;
    const int wid  = tid >> 5;
    const int m0 = blockIdx.x * 128;
    const int n0 = blockIdx.y * 128;
    const int z  = blockIdx.z;

    const unsigned* Bt_g = g_wt3 + ((size_t)z << 20);
    const float* bias = (z == 0) ? bq : (z == 1) ? bk : bv;
    __nv_bfloat16* ohi = g_ohi + (size_t)z * QKV_ELEMS;
    __nv_bfloat16* olo = g_olo + (size_t)z * QKV_ELEMS;

    const int wm = (wid & 1) * 64;
    const int wn = (wid >> 1) * 64;

    float acc[4][8][4];
#pragma unroll
    for (int i = 0; i < 4; i++)
#pragma unroll
        for (int j = 0; j < 8; j++)
#pragma unroll
            for (int l = 0; l < 4; l++) acc[i][j][l] = 0.f;

#define ISSUE(stage, kc)                                                      \
    do {                                                                      \
        unsigned sb_ = sbase + (stage) * QSTAGE;                              \
        _Pragma("unroll")                                                     \
        for (int j = 0; j < 8; j++) {                                         \
            int ch = tid + j * 128;                                           \
            int r = ch >> 3, c16 = ch & 7;                                    \
            unsigned d = sb_ + swz(r, c16);                                   \
            size_t ga = (size_t)(m0 + r) * HIDD + (kc) + c16 * 4;             \
            size_t gb = (size_t)(n0 + r) * HIDD + (kc) + c16 * 4;             \
            cp16(d,         g_xt + ga);                                       \
            cp16(d + ATILE, Bt_g + gb);                                       \
        }                                                                     \
    } while (0)

    ISSUE(0, 0);
    cp_commit();

    const int NCHUNK = HIDD / 32;   // 32
    for (int c = 0; c < NCHUNK; c++) {
        cp_wait0();                  // stage c&1 resident
        __syncthreads();             // orders compute(c-1) reads before overwrite
        if (c + 1 < NCHUNK) {
            ISSUE((c + 1) & 1, (c + 1) * 32);
            cp_commit();
        }

        const unsigned st = sbase + (c & 1) * QSTAGE;
#pragma unroll
        for (int ks = 0; ks < 4; ks++) {       // 4 x k8 per 32-wide chunk
            unsigned a[4][4];
#pragma unroll
            for (int mt = 0; mt < 4; mt++) {
                unsigned aa = st + swz(wm + mt * 16 + (lane & 15),
                                       ks * 2 + (lane >> 4));
                ldm_x4(a[mt], aa);
            }
#pragma unroll
            for (int jb = 0; jb < 4; jb++) {   // pairs of n8 blocks
                unsigned ba = st + ATILE
                            + swz(wn + jb * 16 + ((lane >> 4) << 3) + (lane & 7),
                                  ks * 2 + ((lane >> 3) & 1));
                unsigned bb[4];
                ldm_x4(bb, ba);
#pragma unroll
                for (int mt = 0; mt < 4; mt++) {
                    mma16808(acc[mt][2 * jb],     a[mt], bb[0], bb[1]);
                    mma16808(acc[mt][2 * jb + 1], a[mt], bb[2], bb[3]);
                }
            }
        }
    }

    // Epilogue: frag rows g, g+8; cols 2cc, 2cc+1 -> bf16 hi/lo blocked layout
    const int g  = lane >> 2;
    const int cc = lane & 3;
#pragma unroll
    for (int nt = 0; nt < 8; nt++) {
        const int N = n0 + wn + nt * 8 + cc * 2;
        const int h = N >> 6, d = N & 63;
        float2 bv2 = *(const float2*)&bias[N];
#pragma unroll
        for (int mt = 0; mt < 4; mt++) {
#pragma unroll
            for (int rr = 0; rr < 2; rr++) {
                const int M  = m0 + wm + mt * 16 + g + rr * 8;
                const int b  = M >> 11;
                const int s_ = M & 2047;
                const int nq = s_ >> 6;
                const int ii = s_ & 63;
                size_t idx = ((((size_t)b * Hh + h) * NBQ + nq) << 12) + ii * Dd + d;
                float vx = acc[mt][nt][rr * 2 + 0] + bv2.x;
                float vy = acc[mt][nt][rr * 2 + 1] + bv2.y;
                __nv_bfloat16 hx = __float2bfloat16(vx);
                __nv_bfloat16 hy = __float2bfloat16(vy);
                *(__nv_bfloat162*)(ohi + idx) = __halves2bfloat162(hx, hy);
                *(__nv_bfloat162*)(olo + idx) = __halves2bfloat162(
                    __float2bfloat16(vx - __bfloat162float(hx)),
                    __float2bfloat16(vy - __bfloat162float(hy)));
            }
        }
    }
}

// ---------------------------------------------------------------------------
// Tensor-core flash attention with fixed-max softmax (round-11, 79 us).
// ---------------------------------------------------------------------------
#define ASQH 0
#define ASQL 8192
#define ASKH 16384
#define ASKL 24576
#define ASVH 32768
#define ASVL 40960
#define ATTN_SMEM_BYTES 49152

__global__ __launch_bounds__(128, 3)
void attn_mma_kernel(const float* __restrict__ mask,
                     const int* __restrict__ kidx,
                     float* __restrict__ out)
{
    extern __shared__ char sm[];
    const unsigned sb = smem_u32(sm);
    const int nq = blockIdx.x, h = blockIdx.y, b = blockIdx.z;
    const int tid = threadIdx.x, lane = tid & 31, wid = tid >> 5;
    const int g = lane >> 2, c = lane & 3;
    const int qq = lane >> 3, rl = lane & 7;
    const int wm0 = wid * 16;

    const size_t tbase = (((size_t)b * Hh + h) * NBQ) << 12;
    const __nv_bfloat16* qhi = g_ohi + tbase + ((size_t)nq << 12);
    const __nv_bfloat16* qlo = g_olo + tbase + ((size_t)nq << 12);
    const __nv_bfloat16* khb = g_ohi + QKV_ELEMS + tbase;
    const __nv_bfloat16* klb = g_olo + QKV_ELEMS + tbase;
    const __nv_bfloat16* vhb = g_ohi + 2 * (size_t)QKV_ELEMS + tbase;
    const __nv_bfloat16* vlb = g_olo + 2 * (size_t)QKV_ELEMS + tbase;

    int kvi[KSEL];
    const int* kp = kidx + (h * NBQ + nq) * KSEL;
#pragma unroll
    for (int i = 0; i < KSEL; i++) kvi[i] = kp[i];

#pragma unroll
    for (int j = 0; j < 4; j++) {
        int ch = tid + j * 128;
        int r = ch >> 3, cc16 = ch & 7;
        unsigned o = swz(r, cc16);
        int go = r * 64 + cc16 * 8;
        cp16(sb + ASQH + o, qhi + go);
        cp16(sb + ASQL + o, qlo + go);
    }
    {
        size_t kvo = (size_t)kvi[0] << 12;
#pragma unroll
        for (int j = 0; j < 4; j++) {
            int ch = tid + j * 128;
            int r = ch >> 3, cc16 = ch & 7;
            unsigned o = swz(r, cc16);
            size_t go = kvo + r * 64 + cc16 * 8;
            cp16(sb + ASKH + o, khb + go);
            cp16(sb + ASKL + o, klb + go);
            cp16(sb + ASVH + o, vhb + go);
            cp16(sb + ASVL + o, vlb + go);
        }
    }
    cp_commit();

    float o_acc[8][4];
#pragma unroll
    for (int t = 0; t < 8; t++)
#pragma unroll
        for (int j = 0; j < 4; j++) o_acc[t][j] = 0.f;
    float lsum0 = 0.f, lsum1 = 0.f;

    const int rq0 = nq * BLK + wm0 + g;
    const float* mk0 = mask + (size_t)rq0 * Sseq;
    const float* mk1 = mk0 + 8 * Sseq;

    for (int kb = 0; kb < KSEL; kb++) {
        const int kv64 = kvi[kb] * BLK;
        float2 M0[8], M1[8];
#pragma unroll
        for (int t = 0; t < 8; t++) {
            M0[t] = *(const float2*)&mk0[kv64 + 8 * t + 2 * c];
            M1[t] = *(const float2*)&mk1[kv64 + 8 * t + 2 * c];
        }

        cp_wait0();
        __syncthreads();

        float s[8][4];
#pragma unroll
        for (int t = 0; t < 8; t++)
#pragma unroll
            for (int j = 0; j < 4; j++) s[t][j] = 0.f;

#pragma unroll
        for (int ks = 0; ks < 4; ks++) {
            unsigned ahi[4], alo[4];
            unsigned qa = swz(wm0 + (lane & 15), 2 * ks + (lane >> 4));
            ldm_x4(ahi, sb + ASQH + qa);
            ldm_x4(alo, sb + ASQL + qa);
#pragma unroll
            for (int tp = 0; tp < 4; tp++) {
                unsigned bh[4], bl[4];
                unsigned ka = swz(tp * 16 + rl + ((qq >> 1) << 3), 2 * ks + (qq & 1));
                ldm_x4(bh, sb + ASKH + ka);
                ldm_x4(bl, sb + ASKL + ka);
                mma16816(s[2 * tp],     ahi, bh[0], bh[1]);
                mma16816(s[2 * tp + 1], ahi, bh[2], bh[3]);
                mma16816(s[2 * tp],     ahi, bl[0], bl[1]);
                mma16816(s[2 * tp + 1], ahi, bl[2], bl[3]);
                mma16816(s[2 * tp],     alo, bh[0], bh[1]);
                mma16816(s[2 * tp + 1], alo, bh[2], bh[3]);
            }
        }

#pragma unroll
        for (int t = 0; t < 8; t++) {
            s[t][0] = __expf(s[t][0] * 0.125f * M0[t].x);
            s[t][1] = __expf(s[t][1] * 0.125f * M0[t].y);
            s[t][2] = __expf(s[t][2] * 0.125f * M1[t].x);
            s[t][3] = __expf(s[t][3] * 0.125f * M1[t].y);
            lsum0 += s[t][0] + s[t][1];
            lsum1 += s[t][2] + s[t][3];
        }

#pragma unroll
        for (int ks = 0; ks < 4; ks++) {
            unsigned phi[4], plo[4];
#pragma unroll
            for (int hf = 0; hf < 2; hf++) {
                float p0 = s[2 * ks + hf][0], p1 = s[2 * ks + hf][1];
                float p2 = s[2 * ks + hf][2], p3 = s[2 * ks + hf][3];
                __nv_bfloat16 h0 = __float2bfloat16(p0), h1 = __float2bfloat16(p1);
                __nv_bfloat16 h2 = __float2bfloat16(p2), h3 = __float2bfloat16(p3);
                phi[2 * hf + 0] = b2u(__halves2bfloat162(h0, h1));
                phi[2 * hf + 1] = b2u(__halves2bfloat162(h2, h3));
                plo[2 * hf + 0] = b2u(__halves2bfloat162(
                    __float2bfloat16(p0 - __bfloat162float(h0)),
                    __float2bfloat16(p1 - __bfloat162float(h1))));
                plo[2 * hf + 1] = b2u(__halves2bfloat162(
                    __float2bfloat16(p2 - __bfloat162float(h2)),
                    __float2bfloat16(p3 - __bfloat162float(h3))));
            }
#pragma unroll
            for (int tp = 0; tp < 4; tp++) {
                unsigned vh[4], vl[4];
                unsigned va = swz(16 * ks + rl + ((qq & 1) << 3), 2 * tp + (qq >> 1));
                ldm_x4t(vh, sb + ASVH + va);
                ldm_x4t(vl, sb + ASVL + va);
                mma16816(o_acc[2 * tp],     phi, vh[0], vh[1]);
                mma16816(o_acc[2 * tp + 1], phi, vh[2], vh[3]);
                mma16816(o_acc[2 * tp],     phi, vl[0], vl[1]);
                mma16816(o_acc[2 * tp + 1], phi, vl[2], vl[3]);
                mma16816(o_acc[2 * tp],     plo, vh[0], vh[1]);
                mma16816(o_acc[2 * tp + 1], plo, vh[2], vh[3]);
            }
        }

        __syncthreads();
        if (kb + 1 < KSEL) {
            size_t kvo = (size_t)kvi[kb + 1] << 12;
#pragma unroll
            for (int j = 0; j < 4; j++) {
                int ch = tid + j * 128;
                int r = ch >> 3, cc16 = ch & 7;
                unsigned o = swz(r, cc16);
                size_t go = kvo + r * 64 + cc16 * 8;
                cp16(sb + ASKH + o, khb + go);
                cp16(sb + ASKL + o, klb + go);
                cp16(sb + ASVH + o, vhb + go);
                cp16(sb + ASVL + o, vlb + go);
            }
            cp_commit();
        }
    }

    lsum0 += __shfl_xor_sync(0xFFFFFFFFu, lsum0, 1);
    lsum0 += __shfl_xor_sync(0xFFFFFFFFu, lsum0, 2);
    lsum1 += __shfl_xor_sync(0xFFFFFFFFu, lsum1, 1);
    lsum1 += __shfl_xor_sync(0xFFFFFFFFu, lsum1, 2);

    float i0 = 1.f / lsum0, i1 = 1.f / lsum1;
    float* o0 = out + ((size_t)b * Sseq + rq0) * HIDD + h * Dd;
    float* o1 = o0 + 8 * HIDD;
#pragma unroll
    for (int t = 0; t < 8; t++) {
        *(float2*)&o0[8 * t + 2 * c] = make_float2(o_acc[t][0] * i0, o_acc[t][1] * i0);
        *(float2*)&o1[8 * t + 2 * c] = make_float2(o_acc[t][2] * i1, o_acc[t][3] * i1);
    }
}

// ---------------------------------------------------------------------------
// Launch
// ---------------------------------------------------------------------------
extern "C" void kernel_launch(void* const* d_in, const int* in_sizes, int n_in,
                              void* d_out, int out_size)
{
    const float* X    = (const float*)d_in[0];
    const float* mask = (const float*)d_in[1];
    const int*   kidx = (const int*)d_in[2];
    const float* Wq   = (const float*)d_in[3];
    const float* bq   = (const float*)d_in[4];
    const float* Wk   = (const float*)d_in[5];
    const float* bk   = (const float*)d_in[6];
    const float* Wv   = (const float*)d_in[7];
    const float* bv   = (const float*)d_in[8];
    float* out = (float*)d_out;

    static bool attr_set = false;
    if (!attr_set) {
        cudaFuncSetAttribute(qkv_mma_kernel,
                             cudaFuncAttributeMaxDynamicSharedMemorySize,
                             GEMM_SMEM_BYTES);
        cudaFuncSetAttribute(qkv_mma_kernel,
                             cudaFuncAttributePreferredSharedMemoryCarveout, 100);
        cudaFuncSetAttribute(attn_mma_kernel,
                             cudaFuncAttributeMaxDynamicSharedMemorySize,
                             ATTN_SMEM_BYTES);
        cudaFuncSetAttribute(attn_mma_kernel,
                             cudaFuncAttributePreferredSharedMemoryCarveout, 100);
        attr_set = true;
    }

    cvt_x_kernel<<<(Bsz * Sseq * HIDD) / (256 * 4), 256>>>(X);
    cvt_w_kernel<<<dim3(HIDD / 32, HIDD / 32, 3), dim3(32, 8)>>>(Wq, Wk, Wv);

    dim3 gemm_grid((Bsz * Sseq) / 128, HIDD / 128, 3);
    qkv_mma_kernel<<<gemm_grid, 128, GEMM_SMEM_BYTES>>>(bq, bk, bv);

    dim3 attn_grid(NBQ, Hh, Bsz);
    attn_mma_kernel<<<attn_grid, 128, ATTN_SMEM_BYTES>>>(mask, kidx, out);
}

// round 14
// speedup vs baseline: 1.0635x; 1.0635x over previous
#include <cuda_runtime.h>
#include <cuda_bf16.h>
#include <math.h>

// Problem constants
#define Bsz   2
#define Sseq  2048
#define HIDD  1024
#define Hh    16
#define NBQ   32
#define KSEL  8
#define BLK   64
#define Dd    64

#define QKV_ELEMS (Bsz * Hh * NBQ * BLK * Dd)   // 4,194,304 per tensor

// TF32 GEMM inputs (fp32 payload with tf32 rounding, stored as u32)
__device__ __align__(256) unsigned g_xt[Bsz * Sseq * HIDD];
__device__ __align__(256) unsigned g_wt3[3 * HIDD * HIDD];   // [z][n][k]

// Q,K outputs as tf32-rounded fp32; V as bf16 hi/lo. Layout [b,h,blk][row][d].
__device__ __align__(256) float g_qk32[2 * QKV_ELEMS];
__device__ __align__(256) __nv_bfloat16 g_vhi[QKV_ELEMS];
__device__ __align__(256) __nv_bfloat16 g_vlo[QKV_ELEMS];

// ---------------------------------------------------------------------------
// Generic-PTX helpers
// ---------------------------------------------------------------------------
static __device__ __forceinline__ unsigned smem_u32(const void* p) {
    unsigned a;
    asm("{ .reg .u64 t; cvta.to.shared.u64 t, %1; cvt.u32.u64 %0, t; }"
        : "=r"(a) : "l"(p));
    return a;
}

static __device__ __forceinline__ void cp16(unsigned dst, const void* src) {
    asm volatile("cp.async.cg.shared.global [%0], [%1], 16;"
                 :: "r"(dst), "l"(src));
}
static __device__ __forceinline__ void cp_commit() {
    asm volatile("cp.async.commit_group;");
}
static __device__ __forceinline__ void cp_wait1() {
    asm volatile("cp.async.wait_group 1;" ::: "memory");
}
static __device__ __forceinline__ void cp_wait0() {
    asm volatile("cp.async.wait_group 0;" ::: "memory");
}

static __device__ __forceinline__ void ldm_x4(unsigned r[4], unsigned addr) {
    asm volatile("ldmatrix.sync.aligned.m8n8.x4.shared.b16 {%0,%1,%2,%3}, [%4];"
                 : "=r"(r[0]), "=r"(r[1]), "=r"(r[2]), "=r"(r[3]) : "r"(addr));
}
static __device__ __forceinline__ void ldm_x4t(unsigned r[4], unsigned addr) {
    asm volatile("ldmatrix.sync.aligned.m8n8.x4.trans.shared.b16 {%0,%1,%2,%3}, [%4];"
                 : "=r"(r[0]), "=r"(r[1]), "=r"(r[2]), "=r"(r[3]) : "r"(addr));
}

static __device__ __forceinline__ void mma16816(float c[4], const unsigned a[4],
                                                unsigned b0, unsigned b1) {
    asm volatile(
        "mma.sync.aligned.m16n8k16.row.col.f32.bf16.bf16.f32 "
        "{%0,%1,%2,%3}, {%4,%5,%6,%7}, {%8,%9}, {%0,%1,%2,%3};"
        : "+f"(c[0]), "+f"(c[1]), "+f"(c[2]), "+f"(c[3])
        : "r"(a[0]), "r"(a[1]), "r"(a[2]), "r"(a[3]), "r"(b0), "r"(b1));
}

static __device__ __forceinline__ void mma16808(float c[4], const unsigned a[4],
                                                unsigned b0, unsigned b1) {
    asm volatile(
        "mma.sync.aligned.m16n8k8.row.col.f32.tf32.tf32.f32 "
        "{%0,%1,%2,%3}, {%4,%5,%6,%7}, {%8,%9}, {%0,%1,%2,%3};"
        : "+f"(c[0]), "+f"(c[1]), "+f"(c[2]), "+f"(c[3])
        : "r"(a[0]), "r"(a[1]), "r"(a[2]), "r"(a[3]), "r"(b0), "r"(b1));
}

static __device__ __forceinline__ unsigned f2tf32(float f) {
    unsigned u;
    asm("cvt.rna.tf32.f32 %0, %1;" : "=r"(u) : "f"(f));
    return u;
}

static __device__ __forceinline__ unsigned b2u(__nv_bfloat162 v) {
    return *reinterpret_cast<unsigned*>(&v);
}

// ---------------------------------------------------------------------------
// Conversion kernels: fp32 -> tf32
// ---------------------------------------------------------------------------
__global__ __launch_bounds__(256)
void cvt_x_kernel(const float* __restrict__ X)
{
    int i4 = (blockIdx.x * 256 + threadIdx.x) << 2;
    float4 v = *(const float4*)(X + i4);
    uint4 o;
    o.x = f2tf32(v.x);
    o.y = f2tf32(v.y);
    o.z = f2tf32(v.z);
    o.w = f2tf32(v.w);
    *(uint4*)(g_xt + i4) = o;
}

__global__ __launch_bounds__(256)
void cvt_w_kernel(const float* __restrict__ Wq, const float* __restrict__ Wk,
                  const float* __restrict__ Wv)
{
    __shared__ float t[32][33];
    const float* W = (blockIdx.z == 0) ? Wq : (blockIdx.z == 1) ? Wk : Wv;
    const int k0 = blockIdx.x * 32;
    const int n0 = blockIdx.y * 32;
    const int tx = threadIdx.x;
    const int ty = threadIdx.y;

#pragma unroll
    for (int r = 0; r < 32; r += 8)
        t[ty + r][tx] = W[(size_t)(k0 + ty + r) * HIDD + n0 + tx];
    __syncthreads();

    const size_t ob = ((size_t)blockIdx.z << 20);
#pragma unroll
    for (int r = 0; r < 32; r += 8) {
        g_wt3[ob + (size_t)(n0 + ty + r) * HIDD + k0 + tx] = f2tf32(t[tx][ty + r]);
    }
}

// ---------------------------------------------------------------------------
// QKV GEMM via mma.sync TF32 (round-12 proven config: 3-stage, 2 CTAs/SM).
// Epilogue: Q,K -> tf32-rounded fp32; V -> bf16 hi/lo.
// ---------------------------------------------------------------------------
#define ATILE 16384
#define QSTAGE 32768
#define GEMM_SMEM_BYTES (3 * QSTAGE)     // 98304

// SW128 swizzle (rows/lines of 128 B)
static __device__ __forceinline__ unsigned swz(int r, int c16) {
    return (unsigned)((r << 7) + ((c16 ^ (r & 7)) << 4));
}

__global__ __launch_bounds__(128, 2)
void qkv_mma_kernel(const float* __restrict__ bq, const float* __restrict__ bk,
                    const float* __restrict__ bv)
{
    extern __shared__ char sm[];
    const unsigned sbase = smem_u32(sm);
    const int tid  = threadIdx.x;
    const int lane = tid & 31;
    const int wid  = tid >> 5;
    const int m0 = blockIdx.x * 128;
    const int n0 = blockIdx.y * 128;
    const int z  = blockIdx.z;

    const unsigned* Bt_g = g_wt3 + ((size_t)z << 20);
    const float* bias = (z == 0) ? bq : (z == 1) ? bk : bv;

    const int wm = (wid & 1) * 64;
    const int wn = (wid >> 1) * 64;

    float acc[4][8][4];
#pragma unroll
    for (int i = 0; i < 4; i++)
#pragma unroll
        for (int j = 0; j < 8; j++)
#pragma unroll
            for (int l = 0; l < 4; l++) acc[i][j][l] = 0.f;

#define ISSUE(stage, kc)                                                      \
    do {                                                                      \
        unsigned sb_ = sbase + (stage) * QSTAGE;                              \
        _Pragma("unroll")                                                     \
        for (int j = 0; j < 8; j++) {                                         \
            int ch = tid + j * 128;                                           \
            int r = ch >> 3, c16 = ch & 7;                                    \
            unsigned d = sb_ + swz(r, c16);                                   \
            size_t ga = (size_t)(m0 + r) * HIDD + (kc) + c16 * 4;             \
            size_t gb = (size_t)(n0 + r) * HIDD + (kc) + c16 * 4;             \
            cp16(d,         g_xt + ga);                                       \
            cp16(d + ATILE, Bt_g + gb);                                       \
        }                                                                     \
    } while (0)

    ISSUE(0, 0);
    cp_commit();
    ISSUE(1, 32);
    cp_commit();

    const int NCHUNK = HIDD / 32;   // 32
    for (int c = 0; c < NCHUNK; c++) {
        cp_wait1();
        __syncthreads();
        if (c + 2 < NCHUNK) ISSUE((c + 2) % 3, (c + 2) * 32);
        cp_commit();

        const unsigned st = sbase + (c % 3) * QSTAGE;
#pragma unroll
        for (int ks = 0; ks < 4; ks++) {       // 4 x k8 per 32-wide chunk
            unsigned a[4][4];
#pragma unroll
            for (int mt = 0; mt < 4; mt++) {
                unsigned aa = st + swz(wm + mt * 16 + (lane & 15),
                                       ks * 2 + (lane >> 4));
                ldm_x4(a[mt], aa);
            }
#pragma unroll
            for (int jb = 0; jb < 4; jb++) {   // pairs of n8 blocks
                unsigned ba = st + ATILE
                            + swz(wn + jb * 16 + ((lane >> 4) << 3) + (lane & 7),
                                  ks * 2 + ((lane >> 3) & 1));
                unsigned bb[4];
                ldm_x4(bb, ba);
#pragma unroll
                for (int mt = 0; mt < 4; mt++) {
                    mma16808(acc[mt][2 * jb],     a[mt], bb[0], bb[1]);
                    mma16808(acc[mt][2 * jb + 1], a[mt], bb[2], bb[3]);
                }
            }
        }
    }

    // Epilogue: Q,K -> fp32 (tf32-rounded); V -> bf16 hi/lo
    const int g  = lane >> 2;
    const int cc = lane & 3;
#pragma unroll
    for (int nt = 0; nt < 8; nt++) {
        const int N = n0 + wn + nt * 8 + cc * 2;
        const int h = N >> 6, d = N & 63;
        float2 bv2 = *(const float2*)&bias[N];
#pragma unroll
        for (int mt = 0; mt < 4; mt++) {
#pragma unroll
            for (int rr = 0; rr < 2; rr++) {
                const int M  = m0 + wm + mt * 16 + g + rr * 8;
                const int b  = M >> 11;
                const int s_ = M & 2047;
                const int nq = s_ >> 6;
                const int ii = s_ & 63;
                size_t idx = ((((size_t)b * Hh + h) * NBQ + nq) << 12) + ii * Dd + d;
                float vx = acc[mt][nt][rr * 2 + 0] + bv2.x;
                float vy = acc[mt][nt][rr * 2 + 1] + bv2.y;
                if (z < 2) {
                    uint2 o;
                    o.x = f2tf32(vx);
                    o.y = f2tf32(vy);
                    *(uint2*)(g_qk32 + (size_t)z * QKV_ELEMS + idx) = o;
                } else {
                    __nv_bfloat16 hx = __float2bfloat16(vx);
                    __nv_bfloat16 hy = __float2bfloat16(vy);
                    *(__nv_bfloat162*)(g_vhi + idx) = __halves2bfloat162(hx, hy);
                    *(__nv_bfloat162*)(g_vlo + idx) = __halves2bfloat162(
                        __float2bfloat16(vx - __bfloat162float(hx)),
                        __float2bfloat16(vy - __bfloat162float(hy)));
                }
            }
        }
    }
}

// ---------------------------------------------------------------------------
// Tensor-core flash attention: QK in single-pass TF32, PV in 3-pass bf16,
// fixed-max softmax. Q/K fp32 tiles stored as two 8-KB k-half tiles each.
// Smem 48 KB -> 3 CTAs/SM.
// ---------------------------------------------------------------------------
#define ASQ  0            // Q: half0 @0, half1 @8192   (16 KB)
#define ASK  16384        // K: half0 @16384, half1 @24576 (16 KB)
#define ASVH 32768
#define ASVL 40960
#define ATTN_SMEM_BYTES 49152

__global__ __launch_bounds__(128, 3)
void attn_mma_kernel(const float* __restrict__ mask,
                     const int* __restrict__ kidx,
                     float* __restrict__ out)
{
    extern __shared__ char sm[];
    const unsigned sb = smem_u32(sm);
    const int nq = blockIdx.x, h = blockIdx.y, b = blockIdx.z;
    const int tid = threadIdx.x, lane = tid & 31, wid = tid >> 5;
    const int g = lane >> 2, c = lane & 3;
    const int qq = lane >> 3, rl = lane & 7;
    const int wm0 = wid * 16;

    const size_t tbase = (((size_t)b * Hh + h) * NBQ) << 12;
    const float* qsrc = g_qk32 + tbase + ((size_t)nq << 12);
    const float* kbase = g_qk32 + QKV_ELEMS + tbase;
    const __nv_bfloat16* vhb = g_vhi + tbase;
    const __nv_bfloat16* vlb = g_vlo + tbase;

    int kvi[KSEL];
    const int* kp = kidx + (h * NBQ + nq) * KSEL;
#pragma unroll
    for (int i = 0; i < KSEL; i++) kvi[i] = kp[i];

    // Q loader: 64 rows x 64 fp32 split into two k-half tiles (rows x 32 fp32)
#pragma unroll
    for (int j = 0; j < 8; j++) {
        int ch = tid + j * 128;            // 0..1023
        int r = ch >> 4;                    // row 0..63
        int q16 = ch & 15;                  // 16-B chunk within row
        int hf = q16 >> 3, cc16 = q16 & 7;
        cp16(sb + ASQ + hf * 8192 + swz(r, cc16), qsrc + r * 64 + hf * 32 + cc16 * 4);
    }
    // KV loader for stage kb
#define KVLOAD(kv)                                                            \
    do {                                                                      \
        size_t kvo = (size_t)(kv) << 12;                                      \
        _Pragma("unroll")                                                     \
        for (int j = 0; j < 8; j++) {                                         \
            int ch = tid + j * 128;                                           \
            int r = ch >> 4;                                                  \
            int q16 = ch & 15;                                                \
            int hf = q16 >> 3, cc16 = q16 & 7;                                \
            cp16(sb + ASK + hf * 8192 + swz(r, cc16),                         \
                 kbase + kvo + r * 64 + hf * 32 + cc16 * 4);                  \
        }                                                                     \
        _Pragma("unroll")                                                     \
        for (int j = 0; j < 4; j++) {                                         \
            int ch = tid + j * 128;                                           \
            int r = ch >> 3, cc16 = ch & 7;                                   \
            unsigned o = swz(r, cc16);                                        \
            size_t go = kvo + r * 64 + cc16 * 8;                              \
            cp16(sb + ASVH + o, vhb + go);                                    \
            cp16(sb + ASVL + o, vlb + go);                                    \
        }                                                                     \
    } while (0)

    KVLOAD(kvi[0]);
    cp_commit();

    float o_acc[8][4];
#pragma unroll
    for (int t = 0; t < 8; t++)
#pragma unroll
        for (int j = 0; j < 4; j++) o_acc[t][j] = 0.f;
    float lsum0 = 0.f, lsum1 = 0.f;

    const int rq0 = nq * BLK + wm0 + g;
    const float* mk0 = mask + (size_t)rq0 * Sseq;
    const float* mk1 = mk0 + 8 * Sseq;

    for (int kb = 0; kb < KSEL; kb++) {
        const int kv64 = kvi[kb] * BLK;
        float2 M0[8], M1[8];
#pragma unroll
        for (int t = 0; t < 8; t++) {
            M0[t] = *(const float2*)&mk0[kv64 + 8 * t + 2 * c];
            M1[t] = *(const float2*)&mk1[kv64 + 8 * t + 2 * c];
        }

        cp_wait0();
        __syncthreads();

        // ---- S = Q K^T, single-pass TF32 (8 k8-steps x 8 n8-blocks) ----
        float s[8][4];
#pragma unroll
        for (int t = 0; t < 8; t++)
#pragma unroll
            for (int j = 0; j < 4; j++) s[t][j] = 0.f;

#pragma unroll
        for (int ks = 0; ks < 8; ks++) {
            const unsigned hoff = (ks >> 2) * 8192;
            const int kc = (ks & 3) * 2;
            unsigned a[4];
            ldm_x4(a, sb + ASQ + hoff + swz(wm0 + (lane & 15), kc + (lane >> 4)));
#pragma unroll
            for (int tp = 0; tp < 4; tp++) {
                unsigned bbf[4];
                ldm_x4(bbf, sb + ASK + hoff
                            + swz(tp * 16 + ((lane >> 4) << 3) + (lane & 7),
                                  kc + ((lane >> 3) & 1)));
                mma16808(s[2 * tp],     a, bbf[0], bbf[1]);
                mma16808(s[2 * tp + 1], a, bbf[2], bbf[3]);
            }
        }

        // scale * mask, exp (fixed max = 0), accumulate partial sums
#pragma unroll
        for (int t = 0; t < 8; t++) {
            s[t][0] = __expf(s[t][0] * 0.125f * M0[t].x);
            s[t][1] = __expf(s[t][1] * 0.125f * M0[t].y);
            s[t][2] = __expf(s[t][2] * 0.125f * M1[t].x);
            s[t][3] = __expf(s[t][3] * 0.125f * M1[t].y);
            lsum0 += s[t][0] + s[t][1];
            lsum1 += s[t][2] + s[t][3];
        }

        // ---- O += P V (split bf16, 3 passes) ----
#pragma unroll
        for (int ks = 0; ks < 4; ks++) {
            unsigned phi[4], plo[4];
#pragma unroll
            for (int hf = 0; hf < 2; hf++) {
                float p0 = s[2 * ks + hf][0], p1 = s[2 * ks + hf][1];
                float p2 = s[2 * ks + hf][2], p3 = s[2 * ks + hf][3];
                __nv_bfloat16 h0 = __float2bfloat16(p0), h1 = __float2bfloat16(p1);
                __nv_bfloat16 h2 = __float2bfloat16(p2), h3 = __float2bfloat16(p3);
                phi[2 * hf + 0] = b2u(__halves2bfloat162(h0, h1));
                phi[2 * hf + 1] = b2u(__halves2bfloat162(h2, h3));
                plo[2 * hf + 0] = b2u(__halves2bfloat162(
                    __float2bfloat16(p0 - __bfloat162float(h0)),
                    __float2bfloat16(p1 - __bfloat162float(h1))));
                plo[2 * hf + 1] = b2u(__halves2bfloat162(
                    __float2bfloat16(p2 - __bfloat162float(h2)),
                    __float2bfloat16(p3 - __bfloat162float(h3))));
            }
#pragma unroll
            for (int tp = 0; tp < 4; tp++) {
                unsigned vh[4], vl[4];
                unsigned va = swz(16 * ks + rl + ((qq & 1) << 3), 2 * tp + (qq >> 1));
                ldm_x4t(vh, sb + ASVH + va);
                ldm_x4t(vl, sb + ASVL + va);
                mma16816(o_acc[2 * tp],     phi, vh[0], vh[1]);
                mma16816(o_acc[2 * tp + 1], phi, vh[2], vh[3]);
                mma16816(o_acc[2 * tp],     phi, vl[0], vl[1]);
                mma16816(o_acc[2 * tp + 1], phi, vl[2], vl[3]);
                mma16816(o_acc[2 * tp],     plo, vh[0], vh[1]);
                mma16816(o_acc[2 * tp + 1], plo, vh[2], vh[3]);
            }
        }

        __syncthreads();
        if (kb + 1 < KSEL) KVLOAD(kvi[kb + 1]);
        cp_commit();
    }

    lsum0 += __shfl_xor_sync(0xFFFFFFFFu, lsum0, 1);
    lsum0 += __shfl_xor_sync(0xFFFFFFFFu, lsum0, 2);
    lsum1 += __shfl_xor_sync(0xFFFFFFFFu, lsum1, 1);
    lsum1 += __shfl_xor_sync(0xFFFFFFFFu, lsum1, 2);

    float i0 = 1.f / lsum0, i1 = 1.f / lsum1;
    float* o0 = out + ((size_t)b * Sseq + rq0) * HIDD + h * Dd;
    float* o1 = o0 + 8 * HIDD;
#pragma unroll
    for (int t = 0; t < 8; t++) {
        *(float2*)&o0[8 * t + 2 * c] = make_float2(o_acc[t][0] * i0, o_acc[t][1] * i0);
        *(float2*)&o1[8 * t + 2 * c] = make_float2(o_acc[t][2] * i1, o_acc[t][3] * i1);
    }
}

// ---------------------------------------------------------------------------
// Launch
// ---------------------------------------------------------------------------
extern "C" void kernel_launch(void* const* d_in, const int* in_sizes, int n_in,
                              void* d_out, int out_size)
{
    const float* X    = (const float*)d_in[0];
    const float* mask = (const float*)d_in[1];
    const int*   kidx = (const int*)d_in[2];
    const float* Wq   = (const float*)d_in[3];
    const float* bq   = (const float*)d_in[4];
    const float* Wk   = (const float*)d_in[5];
    const float* bk   = (const float*)d_in[6];
    const float* Wv   = (const float*)d_in[7];
    const float* bv   = (const float*)d_in[8];
    float* out = (float*)d_out;

    static bool attr_set = false;
    if (!attr_set) {
        cudaFuncSetAttribute(qkv_mma_kernel,
                             cudaFuncAttributeMaxDynamicSharedMemorySize,
                             GEMM_SMEM_BYTES);
        cudaFuncSetAttribute(qkv_mma_kernel,
                             cudaFuncAttributePreferredSharedMemoryCarveout, 100);
        cudaFuncSetAttribute(attn_mma_kernel,
                             cudaFuncAttributeMaxDynamicSharedMemorySize,
                             ATTN_SMEM_BYTES);
        cudaFuncSetAttribute(attn_mma_kernel,
                             cudaFuncAttributePreferredSharedMemoryCarveout, 100);
        attr_set = true;
    }

    cvt_x_kernel<<<(Bsz * Sseq * HIDD) / (256 * 4), 256>>>(X);
    cvt_w_kernel<<<dim3(HIDD / 32, HIDD / 32, 3), dim3(32, 8)>>>(Wq, Wk, Wv);

    dim3 gemm_grid((Bsz * Sseq) / 128, HIDD / 128, 3);
    qkv_mma_kernel<<<gemm_grid, 128, GEMM_SMEM_BYTES>>>(bq, bk, bv);

    dim3 attn_grid(NBQ, Hh, Bsz);
    attn_mma_kernel<<<attn_grid, 128, ATTN_SMEM_BYTES>>>(mask, kidx, out);
}

// round 16
// speedup vs baseline: 1.2637x; 1.1883x over previous
#include <cuda_runtime.h>
#include <cuda_bf16.h>
#include <cuda_fp16.h>
#include <math.h>

// Problem constants
#define Bsz   2
#define Sseq  2048
#define HIDD  1024
#define Hh    16
#define NBQ   32
#define KSEL  8
#define BLK   64
#define Dd    64

#define QKV_ELEMS (Bsz * Hh * NBQ * BLK * Dd)   // 4,194,304 per tensor

// fp16 GEMM inputs
__device__ __align__(256) __half g_xh[Bsz * Sseq * HIDD];
__device__ __align__(256) __half g_wh[3 * HIDD * HIDD];   // [z][n][k]

// Q,K outputs as tf32-rounded fp32; V as bf16 hi/lo. Layout [b,h,blk][row][d].
__device__ __align__(256) float g_qk32[2 * QKV_ELEMS];
__device__ __align__(256) __nv_bfloat16 g_vhi[QKV_ELEMS];
__device__ __align__(256) __nv_bfloat16 g_vlo[QKV_ELEMS];

// ---------------------------------------------------------------------------
// Generic-PTX helpers
// ---------------------------------------------------------------------------
static __device__ __forceinline__ unsigned smem_u32(const void* p) {
    unsigned a;
    asm("{ .reg .u64 t; cvta.to.shared.u64 t, %1; cvt.u32.u64 %0, t; }"
        : "=r"(a) : "l"(p));
    return a;
}

static __device__ __forceinline__ void cp16(unsigned dst, const void* src) {
    asm volatile("cp.async.cg.shared.global [%0], [%1], 16;"
                 :: "r"(dst), "l"(src));
}
static __device__ __forceinline__ void cp_commit() {
    asm volatile("cp.async.commit_group;");
}
static __device__ __forceinline__ void cp_wait1() {
    asm volatile("cp.async.wait_group 1;" ::: "memory");
}
static __device__ __forceinline__ void cp_wait0() {
    asm volatile("cp.async.wait_group 0;" ::: "memory");
}

static __device__ __forceinline__ void ldm_x4(unsigned r[4], unsigned addr) {
    asm volatile("ldmatrix.sync.aligned.m8n8.x4.shared.b16 {%0,%1,%2,%3}, [%4];"
                 : "=r"(r[0]), "=r"(r[1]), "=r"(r[2]), "=r"(r[3]) : "r"(addr));
}
static __device__ __forceinline__ void ldm_x4t(unsigned r[4], unsigned addr) {
    asm volatile("ldmatrix.sync.aligned.m8n8.x4.trans.shared.b16 {%0,%1,%2,%3}, [%4];"
                 : "=r"(r[0]), "=r"(r[1]), "=r"(r[2]), "=r"(r[3]) : "r"(addr));
}

static __device__ __forceinline__ void mma16816(float c[4], const unsigned a[4],
                                                unsigned b0, unsigned b1) {
    asm volatile(
        "mma.sync.aligned.m16n8k16.row.col.f32.bf16.bf16.f32 "
        "{%0,%1,%2,%3}, {%4,%5,%6,%7}, {%8,%9}, {%0,%1,%2,%3};"
        : "+f"(c[0]), "+f"(c[1]), "+f"(c[2]), "+f"(c[3])
        : "r"(a[0]), "r"(a[1]), "r"(a[2]), "r"(a[3]), "r"(b0), "r"(b1));
}

static __device__ __forceinline__ void mma16816h(float c[4], const unsigned a[4],
                                                 unsigned b0, unsigned b1) {
    asm volatile(
        "mma.sync.aligned.m16n8k16.row.col.f32.f16.f16.f32 "
        "{%0,%1,%2,%3}, {%4,%5,%6,%7}, {%8,%9}, {%0,%1,%2,%3};"
        : "+f"(c[0]), "+f"(c[1]), "+f"(c[2]), "+f"(c[3])
        : "r"(a[0]), "r"(a[1]), "r"(a[2]), "r"(a[3]), "r"(b0), "r"(b1));
}

static __device__ __forceinline__ void mma16808(float c[4], const unsigned a[4],
                                                unsigned b0, unsigned b1) {
    asm volatile(
        "mma.sync.aligned.m16n8k8.row.col.f32.tf32.tf32.f32 "
        "{%0,%1,%2,%3}, {%4,%5,%6,%7}, {%8,%9}, {%0,%1,%2,%3};"
        : "+f"(c[0]), "+f"(c[1]), "+f"(c[2]), "+f"(c[3])
        : "r"(a[0]), "r"(a[1]), "r"(a[2]), "r"(a[3]), "r"(b0), "r"(b1));
}

static __device__ __forceinline__ unsigned f2tf32(float f) {
    unsigned u;
    asm("cvt.rna.tf32.f32 %0, %1;" : "=r"(u) : "f"(f));
    return u;
}

static __device__ __forceinline__ unsigned b2u(__nv_bfloat162 v) {
    return *reinterpret_cast<unsigned*>(&v);
}

// ---------------------------------------------------------------------------
// Conversion kernels: fp32 -> fp16
// ---------------------------------------------------------------------------
__global__ __launch_bounds__(256)
void cvt_x_kernel(const float* __restrict__ X)
{
    int i4 = (blockIdx.x * 256 + threadIdx.x) << 2;
    float4 v = *(const float4*)(X + i4);
    __half2 h0 = __floats2half2_rn(v.x, v.y);
    __half2 h1 = __floats2half2_rn(v.z, v.w);
    *(__half2*)(g_xh + i4)     = h0;
    *(__half2*)(g_xh + i4 + 2) = h1;
}

__global__ __launch_bounds__(256)
void cvt_w_kernel(const float* __restrict__ Wq, const float* __restrict__ Wk,
                  const float* __restrict__ Wv)
{
    __shared__ float t[32][33];
    const float* W = (blockIdx.z == 0) ? Wq : (blockIdx.z == 1) ? Wk : Wv;
    const int k0 = blockIdx.x * 32;
    const int n0 = blockIdx.y * 32;
    const int tx = threadIdx.x;
    const int ty = threadIdx.y;

#pragma unroll
    for (int r = 0; r < 32; r += 8)
        t[ty + r][tx] = W[(size_t)(k0 + ty + r) * HIDD + n0 + tx];
    __syncthreads();

    const size_t ob = ((size_t)blockIdx.z << 20);
#pragma unroll
    for (int r = 0; r < 32; r += 8) {
        g_wh[ob + (size_t)(n0 + ty + r) * HIDD + k0 + tx] = __float2half_rn(t[tx][ty + r]);
    }
}

// ---------------------------------------------------------------------------
// QKV GEMM via mma.sync FP16 single pass (same 11-bit significand as tf32,
// half the MMA instructions). CTA 128x128, BK=32, 4 warps (2x2), warp 64x64.
// Pair-packed gswz tiles (8 KB each), 3-stage pipeline (48 KB), 3 CTAs/SM.
// ---------------------------------------------------------------------------
#define HTILE 8192
#define HSTAGE (2 * HTILE)               // 16384
#define GEMM_SMEM_BYTES (3 * HSTAGE)     // 49152

// Pair-packed swizzle: rows 2m,2m+1 (64 B each) share 128-B line m.
static __device__ __forceinline__ unsigned gswz(int r, int c16) {
    int line = r >> 1;
    int col  = ((r & 1) << 2) | c16;
    return (unsigned)((line << 7) + ((col ^ (line & 7)) << 4));
}

// SW128 swizzle (rows/lines of 128 B) — used by attention tiles.
static __device__ __forceinline__ unsigned swz(int r, int c16) {
    return (unsigned)((r << 7) + ((c16 ^ (r & 7)) << 4));
}

__global__ __launch_bounds__(128, 3)
void qkv_mma_kernel(const float* __restrict__ bq, const float* __restrict__ bk,
                    const float* __restrict__ bv)
{
    extern __shared__ char sm[];
    const unsigned sbase = smem_u32(sm);
    const int tid  = threadIdx.x;
    const int lane = tid & 31;
    const int wid  = tid >> 5;
    const int m0 = blockIdx.x * 128;
    const int n0 = blockIdx.y * 128;
    const int z  = blockIdx.z;

    const __half* Bh_g = g_wh + ((size_t)z << 20);
    const float* bias = (z == 0) ? bq : (z == 1) ? bk : bv;

    const int wm = (wid & 1) * 64;
    const int wn = (wid >> 1) * 64;
    const int rl = lane & 7;
    const int qq = lane >> 3;

    float acc[4][8][4];
#pragma unroll
    for (int i = 0; i < 4; i++)
#pragma unroll
        for (int j = 0; j < 8; j++)
#pragma unroll
            for (int l = 0; l < 4; l++) acc[i][j][l] = 0.f;

    // Loader: A tile 8 KB (512 x 16B) + B tile 8 KB -> 8 cp16/thread/stage.
#define ISSUE(stage, kc)                                                      \
    do {                                                                      \
        unsigned sb_ = sbase + (stage) * HSTAGE;                              \
        _Pragma("unroll")                                                     \
        for (int j = 0; j < 4; j++) {                                         \
            int ch = tid + j * 128;                                           \
            int r = ch >> 2, c16 = ch & 3;                                    \
            unsigned d = sb_ + gswz(r, c16);                                  \
            size_t ga = (size_t)(m0 + r) * HIDD + (kc) + c16 * 8;             \
            size_t gb = (size_t)(n0 + r) * HIDD + (kc) + c16 * 8;             \
            cp16(d,         g_xh + ga);                                       \
            cp16(d + HTILE, Bh_g + gb);                                       \
        }                                                                     \
    } while (0)

    ISSUE(0, 0);
    cp_commit();
    ISSUE(1, 32);
    cp_commit();

    const int NCHUNK = HIDD / 32;   // 32
    for (int c = 0; c < NCHUNK; c++) {
        cp_wait1();
        __syncthreads();
        if (c + 2 < NCHUNK) ISSUE((c + 2) % 3, (c + 2) * 32);
        cp_commit();

        const unsigned st = sbase + (c % 3) * HSTAGE;
#pragma unroll
        for (int ks = 0; ks < 2; ks++) {       // 2 x k16 per 32-wide chunk
            unsigned a[4][4];
#pragma unroll
            for (int mt = 0; mt < 4; mt++) {
                int arow = wm + mt * 16 + (lane & 15);
                int ac16 = ks * 2 + (lane >> 4);
                ldm_x4(a[mt], st + gswz(arow, ac16));
            }
#pragma unroll
            for (int nt = 0; nt < 4; nt++) {
                int brow = wn + nt * 16 + rl + ((qq >> 1) << 3);
                int bc16 = ks * 2 + (qq & 1);
                unsigned bb[4];
                ldm_x4(bb, st + HTILE + gswz(brow, bc16));
#pragma unroll
                for (int mt = 0; mt < 4; mt++) {
                    mma16816h(acc[mt][2 * nt],     a[mt], bb[0], bb[1]);
                    mma16816h(acc[mt][2 * nt + 1], a[mt], bb[2], bb[3]);
                }
            }
        }
    }

    // Epilogue: Q,K -> fp32 (tf32-rounded); V -> bf16 hi/lo
    const int g  = lane >> 2;
    const int cc = lane & 3;
#pragma unroll
    for (int nt = 0; nt < 8; nt++) {
        const int N = n0 + wn + nt * 8 + cc * 2;
        const int h = N >> 6, d = N & 63;
        float2 bv2 = *(const float2*)&bias[N];
#pragma unroll
        for (int mt = 0; mt < 4; mt++) {
#pragma unroll
            for (int rr = 0; rr < 2; rr++) {
                const int M  = m0 + wm + mt * 16 + g + rr * 8;
                const int b  = M >> 11;
                const int s_ = M & 2047;
                const int nq = s_ >> 6;
                const int ii = s_ & 63;
                size_t idx = ((((size_t)b * Hh + h) * NBQ + nq) << 12) + ii * Dd + d;
                float vx = acc[mt][nt][rr * 2 + 0] + bv2.x;
                float vy = acc[mt][nt][rr * 2 + 1] + bv2.y;
                if (z < 2) {
                    uint2 o;
                    o.x = f2tf32(vx);
                    o.y = f2tf32(vy);
                    *(uint2*)(g_qk32 + (size_t)z * QKV_ELEMS + idx) = o;
                } else {
                    __nv_bfloat16 hx = __float2bfloat16(vx);
                    __nv_bfloat16 hy = __float2bfloat16(vy);
                    *(__nv_bfloat162*)(g_vhi + idx) = __halves2bfloat162(hx, hy);
                    *(__nv_bfloat162*)(g_vlo + idx) = __halves2bfloat162(
                        __float2bfloat16(vx - __bfloat162float(hx)),
                        __float2bfloat16(vy - __bfloat162float(hy)));
                }
            }
        }
    }
}

// ---------------------------------------------------------------------------
// Tensor-core flash attention (round-14 proven, 78 us): QK single-pass TF32,
// PV 3-pass bf16 (Phi x Vhi/Vlo + Plo x Vhi), fixed-max softmax. 48 KB smem.
// ---------------------------------------------------------------------------
#define ASQ  0            // Q: half0 @0, half1 @8192   (16 KB)
#define ASK  16384        // K: half0 @16384, half1 @24576 (16 KB)
#define ASVH 32768
#define ASVL 40960
#define ATTN_SMEM_BYTES 49152

__global__ __launch_bounds__(128, 3)
void attn_mma_kernel(const float* __restrict__ mask,
                     const int* __restrict__ kidx,
                     float* __restrict__ out)
{
    extern __shared__ char sm[];
    const unsigned sb = smem_u32(sm);
    const int nq = blockIdx.x, h = blockIdx.y, b = blockIdx.z;
    const int tid = threadIdx.x, lane = tid & 31, wid = tid >> 5;
    const int g = lane >> 2, c = lane & 3;
    const int qq = lane >> 3, rl = lane & 7;
    const int wm0 = wid * 16;

    const size_t tbase = (((size_t)b * Hh + h) * NBQ) << 12;
    const float* qsrc = g_qk32 + tbase + ((size_t)nq << 12);
    const float* kbase = g_qk32 + QKV_ELEMS + tbase;
    const __nv_bfloat16* vhb = g_vhi + tbase;
    const __nv_bfloat16* vlb = g_vlo + tbase;

    int kvi[KSEL];
    const int* kp = kidx + (h * NBQ + nq) * KSEL;
#pragma unroll
    for (int i = 0; i < KSEL; i++) kvi[i] = kp[i];

#pragma unroll
    for (int j = 0; j < 8; j++) {
        int ch = tid + j * 128;
        int r = ch >> 4;
        int q16 = ch & 15;
        int hf = q16 >> 3, cc16 = q16 & 7;
        cp16(sb + ASQ + hf * 8192 + swz(r, cc16), qsrc + r * 64 + hf * 32 + cc16 * 4);
    }
#define KVLOAD(kv)                                                            \
    do {                                                                      \
        size_t kvo = (size_t)(kv) << 12;                                      \
        _Pragma("unroll")                                                     \
        for (int j = 0; j < 8; j++) {                                         \
            int ch = tid + j * 128;                                           \
            int r = ch >> 4;                                                  \
            int q16 = ch & 15;                                                \
            int hf = q16 >> 3, cc16 = q16 & 7;                                \
            cp16(sb + ASK + hf * 8192 + swz(r, cc16),                         \
                 kbase + kvo + r * 64 + hf * 32 + cc16 * 4);                  \
        }                                                                     \
        _Pragma("unroll")                                                     \
        for (int j = 0; j < 4; j++) {                                         \
            int ch = tid + j * 128;                                           \
            int r = ch >> 3, cc16 = ch & 7;                                   \
            unsigned o = swz(r, cc16);                                        \
            size_t go = kvo + r * 64 + cc16 * 8;                              \
            cp16(sb + ASVH + o, vhb + go);                                    \
            cp16(sb + ASVL + o, vlb + go);                                    \
        }                                                                     \
    } while (0)

    KVLOAD(kvi[0]);
    cp_commit();

    float o_acc[8][4];
#pragma unroll
    for (int t = 0; t < 8; t++)
#pragma unroll
        for (int j = 0; j < 4; j++) o_acc[t][j] = 0.f;
    float lsum0 = 0.f, lsum1 = 0.f;

    const int rq0 = nq * BLK + wm0 + g;
    const float* mk0 = mask + (size_t)rq0 * Sseq;
    const float* mk1 = mk0 + 8 * Sseq;

    for (int kb = 0; kb < KSEL; kb++) {
        const int kv64 = kvi[kb] * BLK;
        float2 M0[8], M1[8];
#pragma unroll
        for (int t = 0; t < 8; t++) {
            M0[t] = *(const float2*)&mk0[kv64 + 8 * t + 2 * c];
            M1[t] = *(const float2*)&mk1[kv64 + 8 * t + 2 * c];
        }

        cp_wait0();
        __syncthreads();

        // ---- S = Q K^T, single-pass TF32 ----
        float s[8][4];
#pragma unroll
        for (int t = 0; t < 8; t++)
#pragma unroll
            for (int j = 0; j < 4; j++) s[t][j] = 0.f;

#pragma unroll
        for (int ks = 0; ks < 8; ks++) {
            const unsigned hoff = (ks >> 2) * 8192;
            const int kc = (ks & 3) * 2;
            unsigned a[4];
            ldm_x4(a, sb + ASQ + hoff + swz(wm0 + (lane & 15), kc + (lane >> 4)));
#pragma unroll
            for (int tp = 0; tp < 4; tp++) {
                unsigned bbf[4];
                ldm_x4(bbf, sb + ASK + hoff
                            + swz(tp * 16 + ((lane >> 4) << 3) + (lane & 7),
                                  kc + ((lane >> 3) & 1)));
                mma16808(s[2 * tp],     a, bbf[0], bbf[1]);
                mma16808(s[2 * tp + 1], a, bbf[2], bbf[3]);
            }
        }

        // scale * mask, exp (fixed max = 0), accumulate partial sums
#pragma unroll
        for (int t = 0; t < 8; t++) {
            s[t][0] = __expf(s[t][0] * 0.125f * M0[t].x);
            s[t][1] = __expf(s[t][1] * 0.125f * M0[t].y);
            s[t][2] = __expf(s[t][2] * 0.125f * M1[t].x);
            s[t][3] = __expf(s[t][3] * 0.125f * M1[t].y);
            lsum0 += s[t][0] + s[t][1];
            lsum1 += s[t][2] + s[t][3];
        }

        // ---- O += P V (split bf16, 3 passes: Phi*Vhi + Phi*Vlo + Plo*Vhi) ----
#pragma unroll
        for (int ks = 0; ks < 4; ks++) {
            unsigned phi[4], plo[4];
#pragma unroll
            for (int hf = 0; hf < 2; hf++) {
                float p0 = s[2 * ks + hf][0], p1 = s[2 * ks + hf][1];
                float p2 = s[2 * ks + hf][2], p3 = s[2 * ks + hf][3];
                __nv_bfloat16 h0 = __float2bfloat16(p0), h1 = __float2bfloat16(p1);
                __nv_bfloat16 h2 = __float2bfloat16(p2), h3 = __float2bfloat16(p3);
                phi[2 * hf + 0] = b2u(__halves2bfloat162(h0, h1));
                phi[2 * hf + 1] = b2u(__halves2bfloat162(h2, h3));
                plo[2 * hf + 0] = b2u(__halves2bfloat162(
                    __float2bfloat16(p0 - __bfloat162float(h0)),
                    __float2bfloat16(p1 - __bfloat162float(h1))));
                plo[2 * hf + 1] = b2u(__halves2bfloat162(
                    __float2bfloat16(p2 - __bfloat162float(h2)),
                    __float2bfloat16(p3 - __bfloat162float(h3))));
            }
#pragma unroll
            for (int tp = 0; tp < 4; tp++) {
                unsigned vh[4], vl[4];
                unsigned va = swz(16 * ks + rl + ((qq & 1) << 3), 2 * tp + (qq >> 1));
                ldm_x4t(vh, sb + ASVH + va);
                ldm_x4t(vl, sb + ASVL + va);
                mma16816(o_acc[2 * tp],     phi, vh[0], vh[1]);
                mma16816(o_acc[2 * tp + 1], phi, vh[2], vh[3]);
                mma16816(o_acc[2 * tp],     phi, vl[0], vl[1]);
                mma16816(o_acc[2 * tp + 1], phi, vl[2], vl[3]);
                mma16816(o_acc[2 * tp],     plo, vh[0], vh[1]);
                mma16816(o_acc[2 * tp + 1], plo, vh[2], vh[3]);
            }
        }

        __syncthreads();
        if (kb + 1 < KSEL) KVLOAD(kvi[kb + 1]);
        cp_commit();
    }

    lsum0 += __shfl_xor_sync(0xFFFFFFFFu, lsum0, 1);
    lsum0 += __shfl_xor_sync(0xFFFFFFFFu, lsum0, 2);
    lsum1 += __shfl_xor_sync(0xFFFFFFFFu, lsum1, 1);
    lsum1 += __shfl_xor_sync(0xFFFFFFFFu, lsum1, 2);

    float i0 = 1.f / lsum0, i1 = 1.f / lsum1;
    float* o0 = out + ((size_t)b * Sseq + rq0) * HIDD + h * Dd;
    float* o1 = o0 + 8 * HIDD;
#pragma unroll
    for (int t = 0; t < 8; t++) {
        *(float2*)&o0[8 * t + 2 * c] = make_float2(o_acc[t][0] * i0, o_acc[t][1] * i0);
        *(float2*)&o1[8 * t + 2 * c] = make_float2(o_acc[t][2] * i1, o_acc[t][3] * i1);
    }
}

// ---------------------------------------------------------------------------
// Launch
// ---------------------------------------------------------------------------
extern "C" void kernel_launch(void* const* d_in, const int* in_sizes, int n_in,
                              void* d_out, int out_size)
{
    const float* X    = (const float*)d_in[0];
    const float* mask = (const float*)d_in[1];
    const int*   kidx = (const int*)d_in[2];
    const float* Wq   = (const float*)d_in[3];
    const float* bq   = (const float*)d_in[4];
    const float* Wk   = (const float*)d_in[5];
    const float* bk   = (const float*)d_in[6];
    const float* Wv   = (const float*)d_in[7];
    const float* bv   = (const float*)d_in[8];
    float* out = (float*)d_out;

    static bool attr_set = false;
    if (!attr_set) {
        cudaFuncSetAttribute(qkv_mma_kernel,
                             cudaFuncAttributeMaxDynamicSharedMemorySize,
                             GEMM_SMEM_BYTES);
        cudaFuncSetAttribute(qkv_mma_kernel,
                             cudaFuncAttributePreferredSharedMemoryCarveout, 100);
        cudaFuncSetAttribute(attn_mma_kernel,
                             cudaFuncAttributeMaxDynamicSharedMemorySize,
                             ATTN_SMEM_BYTES);
        cudaFuncSetAttribute(attn_mma_kernel,
                             cudaFuncAttributePreferredSharedMemoryCarveout, 100);
        attr_set = true;
    }

    cvt_x_kernel<<<(Bsz * Sseq * HIDD) / (256 * 4), 256>>>(X);
    cvt_w_kernel<<<dim3(HIDD / 32, HIDD / 32, 3), dim3(32, 8)>>>(Wq, Wk, Wv);

    dim3 gemm_grid((Bsz * Sseq) / 128, HIDD / 128, 3);
    qkv_mma_kernel<<<gemm_grid, 128, GEMM_SMEM_BYTES>>>(bq, bk, bv);

    dim3 attn_grid(NBQ, Hh, Bsz);
    attn_mma_kernel<<<attn_grid, 128, ATTN_SMEM_BYTES>>>(mask, kidx, out);
}

// round 17
// speedup vs baseline: 1.3112x; 1.0376x over previous
#include <cuda_runtime.h>
#include <cuda_bf16.h>
#include <cuda_fp16.h>
#include <math.h>

// Problem constants
#define Bsz   2
#define Sseq  2048
#define HIDD  1024
#define Hh    16
#define NBQ   32
#define KSEL  8
#define BLK   64
#define Dd    64

#define QKV_ELEMS (Bsz * Hh * NBQ * BLK * Dd)   // 4,194,304 per tensor

// fp16 GEMM inputs
__device__ __align__(256) __half g_xh[Bsz * Sseq * HIDD];
__device__ __align__(256) __half g_wh[3 * HIDD * HIDD];   // [z][n][k]

// Q,K outputs as fp16; V as bf16 hi/lo. Layout [b,h,blk][row][d].
__device__ __align__(256) __half g_qkh[2 * QKV_ELEMS];
__device__ __align__(256) __nv_bfloat16 g_vhi[QKV_ELEMS];
__device__ __align__(256) __nv_bfloat16 g_vlo[QKV_ELEMS];

// ---------------------------------------------------------------------------
// Generic-PTX helpers
// ---------------------------------------------------------------------------
static __device__ __forceinline__ unsigned smem_u32(const void* p) {
    unsigned a;
    asm("{ .reg .u64 t; cvta.to.shared.u64 t, %1; cvt.u32.u64 %0, t; }"
        : "=r"(a) : "l"(p));
    return a;
}

static __device__ __forceinline__ void cp16(unsigned dst, const void* src) {
    asm volatile("cp.async.cg.shared.global [%0], [%1], 16;"
                 :: "r"(dst), "l"(src));
}
static __device__ __forceinline__ void cp_commit() {
    asm volatile("cp.async.commit_group;");
}
static __device__ __forceinline__ void cp_wait2() {
    asm volatile("cp.async.wait_group 2;" ::: "memory");
}
static __device__ __forceinline__ void cp_wait0() {
    asm volatile("cp.async.wait_group 0;" ::: "memory");
}

static __device__ __forceinline__ void ldm_x4(unsigned r[4], unsigned addr) {
    asm volatile("ldmatrix.sync.aligned.m8n8.x4.shared.b16 {%0,%1,%2,%3}, [%4];"
                 : "=r"(r[0]), "=r"(r[1]), "=r"(r[2]), "=r"(r[3]) : "r"(addr));
}
static __device__ __forceinline__ void ldm_x4t(unsigned r[4], unsigned addr) {
    asm volatile("ldmatrix.sync.aligned.m8n8.x4.trans.shared.b16 {%0,%1,%2,%3}, [%4];"
                 : "=r"(r[0]), "=r"(r[1]), "=r"(r[2]), "=r"(r[3]) : "r"(addr));
}

static __device__ __forceinline__ void mma16816(float c[4], const unsigned a[4],
                                                unsigned b0, unsigned b1) {
    asm volatile(
        "mma.sync.aligned.m16n8k16.row.col.f32.bf16.bf16.f32 "
        "{%0,%1,%2,%3}, {%4,%5,%6,%7}, {%8,%9}, {%0,%1,%2,%3};"
        : "+f"(c[0]), "+f"(c[1]), "+f"(c[2]), "+f"(c[3])
        : "r"(a[0]), "r"(a[1]), "r"(a[2]), "r"(a[3]), "r"(b0), "r"(b1));
}

static __device__ __forceinline__ void mma16816h(float c[4], const unsigned a[4],
                                                 unsigned b0, unsigned b1) {
    asm volatile(
        "mma.sync.aligned.m16n8k16.row.col.f32.f16.f16.f32 "
        "{%0,%1,%2,%3}, {%4,%5,%6,%7}, {%8,%9}, {%0,%1,%2,%3};"
        : "+f"(c[0]), "+f"(c[1]), "+f"(c[2]), "+f"(c[3])
        : "r"(a[0]), "r"(a[1]), "r"(a[2]), "r"(a[3]), "r"(b0), "r"(b1));
}

static __device__ __forceinline__ unsigned b2u(__nv_bfloat162 v) {
    return *reinterpret_cast<unsigned*>(&v);
}
static __device__ __forceinline__ unsigned h2u(__half2 v) {
    return *reinterpret_cast<unsigned*>(&v);
}

// ---------------------------------------------------------------------------
// Conversion kernels: fp32 -> fp16
// ---------------------------------------------------------------------------
__global__ __launch_bounds__(256)
void cvt_x_kernel(const float* __restrict__ X)
{
    int i4 = (blockIdx.x * 256 + threadIdx.x) << 2;
    float4 v = *(const float4*)(X + i4);
    *(__half2*)(g_xh + i4)     = __floats2half2_rn(v.x, v.y);
    *(__half2*)(g_xh + i4 + 2) = __floats2half2_rn(v.z, v.w);
}

__global__ __launch_bounds__(256)
void cvt_w_kernel(const float* __restrict__ Wq, const float* __restrict__ Wk,
                  const float* __restrict__ Wv)
{
    __shared__ float t[32][33];
    const float* W = (blockIdx.z == 0) ? Wq : (blockIdx.z == 1) ? Wk : Wv;
    const int k0 = blockIdx.x * 32;
    const int n0 = blockIdx.y * 32;
    const int tx = threadIdx.x;
    const int ty = threadIdx.y;

#pragma unroll
    for (int r = 0; r < 32; r += 8)
        t[ty + r][tx] = W[(size_t)(k0 + ty + r) * HIDD + n0 + tx];
    __syncthreads();

    const size_t ob = ((size_t)blockIdx.z << 20);
#pragma unroll
    for (int r = 0; r < 32; r += 8) {
        g_wh[ob + (size_t)(n0 + ty + r) * HIDD + k0 + tx] = __float2half_rn(t[tx][ty + r]);
    }
}

// ---------------------------------------------------------------------------
// QKV GEMM via mma.sync FP16 single pass. CTA 128x128, BK=32, 4 warps (2x2),
// warp 64x64. 4-stage pipeline (64 KB, 3-deep prefetch), 3 CTAs/SM.
// ---------------------------------------------------------------------------
#define HTILE 8192
#define HSTAGE (2 * HTILE)               // 16384
#define GEMM_SMEM_BYTES (4 * HSTAGE)     // 65536

// Pair-packed swizzle: rows 2m,2m+1 (64 B each) share 128-B line m.
static __device__ __forceinline__ unsigned gswz(int r, int c16) {
    int line = r >> 1;
    int col  = ((r & 1) << 2) | c16;
    return (unsigned)((line << 7) + ((col ^ (line & 7)) << 4));
}

// SW128 swizzle (rows/lines of 128 B) — attention tiles.
static __device__ __forceinline__ unsigned swz(int r, int c16) {
    return (unsigned)((r << 7) + ((c16 ^ (r & 7)) << 4));
}

__global__ __launch_bounds__(128, 3)
void qkv_mma_kernel(const float* __restrict__ bq, const float* __restrict__ bk,
                    const float* __restrict__ bv)
{
    extern __shared__ char sm[];
    const unsigned sbase = smem_u32(sm);
    const int tid  = threadIdx.x;
    const int lane = tid & 31;
    const int wid  = tid >> 5;
    const int m0 = blockIdx.x * 128;
    const int n0 = blockIdx.y * 128;
    const int z  = blockIdx.z;

    const __half* Bh_g = g_wh + ((size_t)z << 20);
    const float* bias = (z == 0) ? bq : (z == 1) ? bk : bv;

    const int wm = (wid & 1) * 64;
    const int wn = (wid >> 1) * 64;
    const int rl = lane & 7;
    const int qq = lane >> 3;

    float acc[4][8][4];
#pragma unroll
    for (int i = 0; i < 4; i++)
#pragma unroll
        for (int j = 0; j < 8; j++)
#pragma unroll
            for (int l = 0; l < 4; l++) acc[i][j][l] = 0.f;

#define ISSUE(stage, kc)                                                      \
    do {                                                                      \
        unsigned sb_ = sbase + (stage) * HSTAGE;                              \
        _Pragma("unroll")                                                     \
        for (int j = 0; j < 4; j++) {                                         \
            int ch = tid + j * 128;                                           \
            int r = ch >> 2, c16 = ch & 3;                                    \
            unsigned d = sb_ + gswz(r, c16);                                  \
            size_t ga = (size_t)(m0 + r) * HIDD + (kc) + c16 * 8;             \
            size_t gb = (size_t)(n0 + r) * HIDD + (kc) + c16 * 8;             \
            cp16(d,         g_xh + ga);                                       \
            cp16(d + HTILE, Bh_g + gb);                                       \
        }                                                                     \
    } while (0)

    ISSUE(0, 0);
    cp_commit();
    ISSUE(1, 32);
    cp_commit();
    ISSUE(2, 64);
    cp_commit();

    const int NCHUNK = HIDD / 32;   // 32
    for (int c = 0; c < NCHUNK; c++) {
        cp_wait2();                  // chunk c resident (c+1, c+2 may fly)
        __syncthreads();             // readers of stage (c-1)&3 done globally
        if (c + 3 < NCHUNK) ISSUE((c + 3) & 3, (c + 3) * 32);
        cp_commit();                 // one group per iteration (possibly empty)

        const unsigned st = sbase + (c & 3) * HSTAGE;
#pragma unroll
        for (int ks = 0; ks < 2; ks++) {       // 2 x k16 per 32-wide chunk
            unsigned a[4][4];
#pragma unroll
            for (int mt = 0; mt < 4; mt++) {
                int arow = wm + mt * 16 + (lane & 15);
                int ac16 = ks * 2 + (lane >> 4);
                ldm_x4(a[mt], st + gswz(arow, ac16));
            }
#pragma unroll
            for (int nt = 0; nt < 4; nt++) {
                int brow = wn + nt * 16 + rl + ((qq >> 1) << 3);
                int bc16 = ks * 2 + (qq & 1);
                unsigned bb[4];
                ldm_x4(bb, st + HTILE + gswz(brow, bc16));
#pragma unroll
                for (int mt = 0; mt < 4; mt++) {
                    mma16816h(acc[mt][2 * nt],     a[mt], bb[0], bb[1]);
                    mma16816h(acc[mt][2 * nt + 1], a[mt], bb[2], bb[3]);
                }
            }
        }
    }

    // Epilogue: Q,K -> fp16; V -> bf16 hi/lo
    const int g  = lane >> 2;
    const int cc = lane & 3;
#pragma unroll
    for (int nt = 0; nt < 8; nt++) {
        const int N = n0 + wn + nt * 8 + cc * 2;
        const int h = N >> 6, d = N & 63;
        float2 bv2 = *(const float2*)&bias[N];
#pragma unroll
        for (int mt = 0; mt < 4; mt++) {
#pragma unroll
            for (int rr = 0; rr < 2; rr++) {
                const int M  = m0 + wm + mt * 16 + g + rr * 8;
                const int b  = M >> 11;
                const int s_ = M & 2047;
                const int nq = s_ >> 6;
                const int ii = s_ & 63;
                size_t idx = ((((size_t)b * Hh + h) * NBQ + nq) << 12) + ii * Dd + d;
                float vx = acc[mt][nt][rr * 2 + 0] + bv2.x;
                float vy = acc[mt][nt][rr * 2 + 1] + bv2.y;
                if (z < 2) {
                    *(__half2*)(g_qkh + (size_t)z * QKV_ELEMS + idx) =
                        __floats2half2_rn(vx, vy);
                } else {
                    __nv_bfloat16 hx = __float2bfloat16(vx);
                    __nv_bfloat16 hy = __float2bfloat16(vy);
                    *(__nv_bfloat162*)(g_vhi + idx) = __halves2bfloat162(hx, hy);
                    *(__nv_bfloat162*)(g_vlo + idx) = __halves2bfloat162(
                        __float2bfloat16(vx - __bfloat162float(hx)),
                        __float2bfloat16(vy - __bfloat162float(hy)));
                }
            }
        }
    }
}

// ---------------------------------------------------------------------------
// Tensor-core flash attention: QK single-pass FP16 (32 MMA/kb/warp),
// PV 3-pass bf16, fixed-max softmax. Smem 32 KB.
// ---------------------------------------------------------------------------
#define ASQ  0            // Q fp16 64x64 (8 KB)
#define ASK  8192         // K fp16 64x64 (8 KB)
#define ASVH 16384
#define ASVL 24576
#define ATTN_SMEM_BYTES 32768

__global__ __launch_bounds__(128, 3)
void attn_mma_kernel(const float* __restrict__ mask,
                     const int* __restrict__ kidx,
                     float* __restrict__ out)
{
    extern __shared__ char sm[];
    const unsigned sb = smem_u32(sm);
    const int nq = blockIdx.x, h = blockIdx.y, b = blockIdx.z;
    const int tid = threadIdx.x, lane = tid & 31, wid = tid >> 5;
    const int g = lane >> 2, c = lane & 3;
    const int qq = lane >> 3, rl = lane & 7;
    const int wm0 = wid * 16;

    const size_t tbase = (((size_t)b * Hh + h) * NBQ) << 12;
    const __half* qh = g_qkh + tbase + ((size_t)nq << 12);
    const __half* khb = g_qkh + QKV_ELEMS + tbase;
    const __nv_bfloat16* vhb = g_vhi + tbase;
    const __nv_bfloat16* vlb = g_vlo + tbase;

    int kvi[KSEL];
    const int* kp = kidx + (h * NBQ + nq) * KSEL;
#pragma unroll
    for (int i = 0; i < KSEL; i++) kvi[i] = kp[i];

    // Q loader: 64 rows x 64 fp16 (128-B rows), SW128 swizzle
#pragma unroll
    for (int j = 0; j < 4; j++) {
        int ch = tid + j * 128;
        int r = ch >> 3, cc16 = ch & 7;
        cp16(sb + ASQ + swz(r, cc16), qh + r * 64 + cc16 * 8);
    }
#define KVLOAD(kv)                                                            \
    do {                                                                      \
        size_t kvo = (size_t)(kv) << 12;                                      \
        _Pragma("unroll")                                                     \
        for (int j = 0; j < 4; j++) {                                         \
            int ch = tid + j * 128;                                           \
            int r = ch >> 3, cc16 = ch & 7;                                   \
            unsigned o = swz(r, cc16);                                        \
            cp16(sb + ASK + o, khb + kvo + r * 64 + cc16 * 8);                \
            cp16(sb + ASVH + o, vhb + kvo + r * 64 + cc16 * 8);               \
            cp16(sb + ASVL + o, vlb + kvo + r * 64 + cc16 * 8);               \
        }                                                                     \
    } while (0)

    KVLOAD(kvi[0]);
    cp_commit();

    float o_acc[8][4];
#pragma unroll
    for (int t = 0; t < 8; t++)
#pragma unroll
        for (int j = 0; j < 4; j++) o_acc[t][j] = 0.f;
    float lsum0 = 0.f, lsum1 = 0.f;

    const int rq0 = nq * BLK + wm0 + g;
    const float* mk0 = mask + (size_t)rq0 * Sseq;
    const float* mk1 = mk0 + 8 * Sseq;

    for (int kb = 0; kb < KSEL; kb++) {
        const int kv64 = kvi[kb] * BLK;
        float2 M0[8], M1[8];
#pragma unroll
        for (int t = 0; t < 8; t++) {
            M0[t] = *(const float2*)&mk0[kv64 + 8 * t + 2 * c];
            M1[t] = *(const float2*)&mk1[kv64 + 8 * t + 2 * c];
        }

        cp_wait0();
        __syncthreads();

        // ---- S = Q K^T, single-pass FP16 (4 k16-steps x 8 n8-blocks) ----
        float s[8][4];
#pragma unroll
        for (int t = 0; t < 8; t++)
#pragma unroll
            for (int j = 0; j < 4; j++) s[t][j] = 0.f;

#pragma unroll
        for (int ks = 0; ks < 4; ks++) {
            unsigned a[4];
            ldm_x4(a, sb + ASQ + swz(wm0 + (lane & 15), 2 * ks + (lane >> 4)));
#pragma unroll
            for (int tp = 0; tp < 4; tp++) {
                unsigned bb[4];
                ldm_x4(bb, sb + ASK + swz(tp * 16 + rl + ((qq >> 1) << 3),
                                          2 * ks + (qq & 1)));
                mma16816h(s[2 * tp],     a, bb[0], bb[1]);
                mma16816h(s[2 * tp + 1], a, bb[2], bb[3]);
            }
        }

        // scale * mask, exp (fixed max = 0), accumulate partial sums
#pragma unroll
        for (int t = 0; t < 8; t++) {
            s[t][0] = __expf(s[t][0] * 0.125f * M0[t].x);
            s[t][1] = __expf(s[t][1] * 0.125f * M0[t].y);
            s[t][2] = __expf(s[t][2] * 0.125f * M1[t].x);
            s[t][3] = __expf(s[t][3] * 0.125f * M1[t].y);
            lsum0 += s[t][0] + s[t][1];
            lsum1 += s[t][2] + s[t][3];
        }

        // ---- O += P V (split bf16, 3 passes: Phi*Vhi + Phi*Vlo + Plo*Vhi) ----
#pragma unroll
        for (int ks = 0; ks < 4; ks++) {
            unsigned phi[4], plo[4];
#pragma unroll
            for (int hf = 0; hf < 2; hf++) {
                float p0 = s[2 * ks + hf][0], p1 = s[2 * ks + hf][1];
                float p2 = s[2 * ks + hf][2], p3 = s[2 * ks + hf][3];
                __nv_bfloat16 h0 = __float2bfloat16(p0), h1 = __float2bfloat16(p1);
                __nv_bfloat16 h2 = __float2bfloat16(p2), h3 = __float2bfloat16(p3);
                phi[2 * hf + 0] = b2u(__halves2bfloat162(h0, h1));
                phi[2 * hf + 1] = b2u(__halves2bfloat162(h2, h3));
                plo[2 * hf + 0] = b2u(__halves2bfloat162(
                    __float2bfloat16(p0 - __bfloat162float(h0)),
                    __float2bfloat16(p1 - __bfloat162float(h1))));
                plo[2 * hf + 1] = b2u(__halves2bfloat162(
                    __float2bfloat16(p2 - __bfloat162float(h2)),
                    __float2bfloat16(p3 - __bfloat162float(h3))));
            }
#pragma unroll
            for (int tp = 0; tp < 4; tp++) {
                unsigned vh[4], vl[4];
                unsigned va = swz(16 * ks + rl + ((qq & 1) << 3), 2 * tp + (qq >> 1));
                ldm_x4t(vh, sb + ASVH + va);
                ldm_x4t(vl, sb + ASVL + va);
                mma16816(o_acc[2 * tp],     phi, vh[0], vh[1]);
                mma16816(o_acc[2 * tp + 1], phi, vh[2], vh[3]);
                mma16816(o_acc[2 * tp],     phi, vl[0], vl[1]);
                mma16816(o_acc[2 * tp + 1], phi, vl[2], vl[3]);
                mma16816(o_acc[2 * tp],     plo, vh[0], vh[1]);
                mma16816(o_acc[2 * tp + 1], plo, vh[2], vh[3]);
            }
        }

        __syncthreads();
        if (kb + 1 < KSEL) KVLOAD(kvi[kb + 1]);
        cp_commit();
    }

    lsum0 += __shfl_xor_sync(0xFFFFFFFFu, lsum0, 1);
    lsum0 += __shfl_xor_sync(0xFFFFFFFFu, lsum0, 2);
    lsum1 += __shfl_xor_sync(0xFFFFFFFFu, lsum1, 1);
    lsum1 += __shfl_xor_sync(0xFFFFFFFFu, lsum1, 2);

    float i0 = 1.f / lsum0, i1 = 1.f / lsum1;
    float* o0 = out + ((size_t)b * Sseq + rq0) * HIDD + h * Dd;
    float* o1 = o0 + 8 * HIDD;
#pragma unroll
    for (int t = 0; t < 8; t++) {
        *(float2*)&o0[8 * t + 2 * c] = make_float2(o_acc[t][0] * i0, o_acc[t][1] * i0);
        *(float2*)&o1[8 * t + 2 * c] = make_float2(o_acc[t][2] * i1, o_acc[t][3] * i1);
    }
}

// ---------------------------------------------------------------------------
// Launch
// ---------------------------------------------------------------------------
extern "C" void kernel_launch(void* const* d_in, const int* in_sizes, int n_in,
                              void* d_out, int out_size)
{
    const float* X    = (const float*)d_in[0];
    const float* mask = (const float*)d_in[1];
    const int*   kidx = (const int*)d_in[2];
    const float* Wq   = (const float*)d_in[3];
    const float* bq   = (const float*)d_in[4];
    const float* Wk   = (const float*)d_in[5];
    const float* bk   = (const float*)d_in[6];
    const float* Wv   = (const float*)d_in[7];
    const float* bv   = (const float*)d_in[8];
    float* out = (float*)d_out;

    static bool attr_set = false;
    if (!attr_set) {
        cudaFuncSetAttribute(qkv_mma_kernel,
                             cudaFuncAttributeMaxDynamicSharedMemorySize,
                             GEMM_SMEM_BYTES);
        cudaFuncSetAttribute(qkv_mma_kernel,
                             cudaFuncAttributePreferredSharedMemoryCarveout, 100);
        cudaFuncSetAttribute(attn_mma_kernel,
                             cudaFuncAttributeMaxDynamicSharedMemorySize,
                             ATTN_SMEM_BYTES);
        cudaFuncSetAttribute(attn_mma_kernel,
                             cudaFuncAttributePreferredSharedMemoryCarveout, 100);
        attr_set = true;
    }

    cvt_x_kernel<<<(Bsz * Sseq * HIDD) / (256 * 4), 256>>>(X);
    cvt_w_kernel<<<dim3(HIDD / 32, HIDD / 32, 3), dim3(32, 8)>>>(Wq, Wk, Wv);

    dim3 gemm_grid((Bsz * Sseq) / 128, HIDD / 128, 3);
    qkv_mma_kernel<<<gemm_grid, 128, GEMM_SMEM_BYTES>>>(bq, bk, bv);

    dim3 attn_grid(NBQ, Hh, Bsz);
    attn_mma_kernel<<<attn_grid, 128, ATTN_SMEM_BYTES>>>(mask, kidx, out);
}